// round 2
// baseline (speedup 1.0000x reference)
#include <cuda_runtime.h>
#include <cuda_bf16.h>
#include <math.h>

// AR(16) simulation, batch=4096, steps=8192.
// Strategy: the recurrence is a stable linear system (char. roots |z| <= 1/1.1),
// so state influence decays ~0.909^k. Split the 8176 noise steps into 16
// segments; each segment (except the first) is computed independently after a
// 256-step warm-up on the preceding noise (residual coupling ~2.5e-11).
// 65K threads -> ~3.5 warps/SMSP, FFMA-throughput bound.
// Outputs staged in padded smem and flushed transposed for coalesced STG.

#define AR_N     16
#define BATCH    4096
#define STEPS    8192
#define TNOISE   (STEPS - AR_N)   /* 8176 */
#define NSEG     16
#define SEGLEN   512              /* last segment: 8176 - 15*512 = 496 */
#define WARM     256
#define BT       128              /* batch rows per block */

__global__ __launch_bounds__(BT) void ar_segmented_kernel(
    const float* __restrict__ iv,     // (BATCH, 16)
    const float* __restrict__ coef,   // (16,)
    const float* __restrict__ lns,    // (1,)
    const float* __restrict__ noise,  // (TNOISE, BATCH)
    float* __restrict__ out)          // (BATCH, STEPS)
{
    // double-buffered staging tile; row stride 17 -> conflict-free banks
    __shared__ float tile[2][BT][AR_N + 1];

    const int tid = threadIdx.x;
    const int b   = blockIdx.x * BT + tid;
    const int s   = blockIdx.y;
    const int t0  = s * SEGLEN;
    const int len = (s == NSEG - 1) ? (TNOISE - t0) : SEGLEN;  // 512 or 496
    const float nstd = expf(lns[0]);

    float c[AR_N];
#pragma unroll
    for (int i = 0; i < AR_N; i++) c[i] = __ldg(&coef[i]);

    float h[AR_N];  // circular history; at block boundaries h[i] = logical elem i (0=oldest)

    if (s == 0) {
        // exact initial history; also emit the first 16 output values
#pragma unroll
        for (int i = 0; i < AR_N; i++) {
            h[i] = iv[b * AR_N + i];
            out[(size_t)b * STEPS + i] = h[i];
        }
    } else {
        // zero-init + warm-up on the WARM preceding noise steps
#pragma unroll
        for (int i = 0; i < AR_N; i++) h[i] = 0.f;
        const float* np = noise + (size_t)(t0 - WARM) * BATCH + b;
#pragma unroll 1
        for (int blk = 0; blk < WARM / AR_N; blk++) {
            float e[AR_N];
#pragma unroll
            for (int k = 0; k < AR_N; k++) e[k] = np[(size_t)k * BATCH];
            np += (size_t)AR_N * BATCH;
#pragma unroll
            for (int k = 0; k < AR_N; k++) {
                float a0 = e[k] * nstd, a1 = 0.f, a2 = 0.f, a3 = 0.f;
#pragma unroll
                for (int i = 0; i < AR_N; i += 4) {
                    a0 = fmaf(c[i + 0], h[(k + i + 0) & (AR_N - 1)], a0);
                    a1 = fmaf(c[i + 1], h[(k + i + 1) & (AR_N - 1)], a1);
                    a2 = fmaf(c[i + 2], h[(k + i + 2) & (AR_N - 1)], a2);
                    a3 = fmaf(c[i + 3], h[(k + i + 3) & (AR_N - 1)], a3);
                }
                h[k & (AR_N - 1)] = (a0 + a1) + (a2 + a3);
            }
        }
    }

    // main segment: compute + stage + coalesced flush every 16 steps
    const float* np = noise + (size_t)t0 * BATCH + b;
    const int nblk = len / AR_N;  // 32 (or 31 for last segment)
    const int rowbase = blockIdx.x * BT;

#pragma unroll 1
    for (int blk = 0; blk < nblk; blk++) {
        float e[AR_N];
#pragma unroll
        for (int k = 0; k < AR_N; k++) e[k] = np[(size_t)k * BATCH];
        np += (size_t)AR_N * BATCH;

        const int p = blk & 1;
#pragma unroll
        for (int k = 0; k < AR_N; k++) {
            float a0 = e[k] * nstd, a1 = 0.f, a2 = 0.f, a3 = 0.f;
#pragma unroll
            for (int i = 0; i < AR_N; i += 4) {
                a0 = fmaf(c[i + 0], h[(k + i + 0) & (AR_N - 1)], a0);
                a1 = fmaf(c[i + 1], h[(k + i + 1) & (AR_N - 1)], a1);
                a2 = fmaf(c[i + 2], h[(k + i + 2) & (AR_N - 1)], a2);
                a3 = fmaf(c[i + 3], h[(k + i + 3) & (AR_N - 1)], a3);
            }
            float nv = (a0 + a1) + (a2 + a3);
            h[k & (AR_N - 1)] = nv;
            tile[p][tid][k] = nv;
        }
        __syncthreads();

        // transpose-flush: 2048 floats; 16 consecutive lanes cover one row's
        // 16 consecutive outputs (64B contiguous) -> coalesced
        const int outbase = AR_N + t0 + blk * AR_N;
#pragma unroll
        for (int j = 0; j < AR_N; j++) {
            int fid = j * BT + tid;
            int row = fid >> 4;
            int col = fid & 15;
            out[(size_t)(rowbase + row) * STEPS + outbase + col] = tile[p][row][col];
        }
        // no trailing sync needed: double-buffered tile; the next iteration's
        // barrier orders this flush's reads before buffer reuse
    }
}

extern "C" void kernel_launch(void* const* d_in, const int* in_sizes, int n_in,
                              void* d_out, int out_size)
{
    const float* iv    = (const float*)d_in[0];
    const float* coef  = (const float*)d_in[1];
    const float* lns   = (const float*)d_in[2];
    const float* noise = (const float*)d_in[3];
    float* out = (float*)d_out;

    dim3 grid(BATCH / BT, NSEG);
    ar_segmented_kernel<<<grid, BT>>>(iv, coef, lns, noise, out);
}

// round 4
// speedup vs baseline: 1.2333x; 1.2333x over previous
#include <cuda_runtime.h>
#include <cuda_bf16.h>
#include <math.h>

// AR(16), batch=4096, steps=8192. Segment-parallel: stable system (|roots|>=1.1
// => state decay <= 0.909/step). 32 time segments; segments 1..31 start from a
// zero state and warm up on the 192 preceding noise steps (residual ~1e-8).
// R3 changes vs R2: NSEG 16->32 (occ 20.5%->~43%) and software-pipelined noise
// prefetch (ping-pong register buffers) to kill the exposed DRAM stall per
// 16-step block. Outputs staged in padded smem, flushed transposed (coalesced).

#define AR_N     16
#define BATCH    4096
#define STEPS    8192
#define TNOISE   (STEPS - AR_N)   /* 8176 */
#define NSEG     32
#define SEGLEN   256              /* last segment: 8176 - 31*256 = 240 */
#define WARM     192              /* (1/1.1)^192 ~ 1e-8 */
#define BT       128              /* batch rows per block */

__device__ __forceinline__ void load16(float e[AR_N], const float* __restrict__ p)
{
#pragma unroll
    for (int k = 0; k < AR_N; k++) e[k] = p[(size_t)k * BATCH];
}

// 16 recurrence steps. Newest history value is consumed in the LAST fma of the
// a3 chain, so the inter-step critical path is fma(4)+add(4)+add(4) = 12 cyc.
template <bool EMIT>
__device__ __forceinline__ void steps16(float h[AR_N], const float e[AR_N],
                                        const float c[AR_N], float nstd,
                                        float* __restrict__ stage)
{
#pragma unroll
    for (int k = 0; k < AR_N; k++) {
        float a0 = e[k] * nstd, a1 = 0.f, a2 = 0.f, a3 = 0.f;
#pragma unroll
        for (int i = 0; i < AR_N; i += 4) {
            a0 = fmaf(c[i + 0], h[(k + i + 0) & (AR_N - 1)], a0);
            a1 = fmaf(c[i + 1], h[(k + i + 1) & (AR_N - 1)], a1);
            a2 = fmaf(c[i + 2], h[(k + i + 2) & (AR_N - 1)], a2);
            a3 = fmaf(c[i + 3], h[(k + i + 3) & (AR_N - 1)], a3);
        }
        float nv = (a0 + a1) + (a2 + a3);
        h[k & (AR_N - 1)] = nv;
        if (EMIT) stage[k] = nv;
    }
}

__global__ __launch_bounds__(BT) void ar_segmented_kernel(
    const float* __restrict__ iv,     // (BATCH, 16)
    const float* __restrict__ coef,   // (16,)
    const float* __restrict__ lns,    // (1,)
    const float* __restrict__ noise,  // (TNOISE, BATCH)
    float* __restrict__ out)          // (BATCH, STEPS)
{
    __shared__ float tile[2][BT][AR_N + 1];  // stride 17 -> conflict-free

    const int tid = threadIdx.x;
    const int b   = blockIdx.x * BT + tid;
    const int s   = blockIdx.y;
    const int t0  = s * SEGLEN;
    const int len = (s == NSEG - 1) ? (TNOISE - t0) : SEGLEN;  // 256 or 240
    const float nstd = expf(lns[0]);
    const int rowbase = blockIdx.x * BT;

    float c[AR_N];
#pragma unroll
    for (int i = 0; i < AR_N; i++) c[i] = __ldg(&coef[i]);

    float h[AR_N];
    int warmblk;
    const float* np;

    if (s == 0) {
        warmblk = 0;
        np = noise + b;
#pragma unroll
        for (int i = 0; i < AR_N; i++) {
            h[i] = iv[b * AR_N + i];
            out[(size_t)b * STEPS + i] = h[i];
        }
    } else {
        warmblk = WARM / AR_N;  // 12
        np = noise + (size_t)(t0 - WARM) * BATCH + b;
#pragma unroll
        for (int i = 0; i < AR_N; i++) h[i] = 0.f;
    }

    const int nblk = warmblk + len / AR_N;  // 16 / 28 / 27
    const size_t nstride = (size_t)AR_N * BATCH;

    float ea[AR_N], eb[AR_N];
    load16(ea, np); np += nstride;

    // process one 16-step block (compute + optional staged/coalesced flush)
    auto process = [&](const float e[AR_N], int blk) {
        if (blk >= warmblk) {
            const int p = blk & 1;
            steps16<true>(h, e, c, nstd, &tile[p][tid][0]);
            __syncthreads();
            const int outbase = AR_N + t0 + (blk - warmblk) * AR_N;
#pragma unroll
            for (int j = 0; j < AR_N; j++) {
                int fid = j * BT + tid;
                int row = fid >> 4;
                int col = fid & 15;
                out[(size_t)(rowbase + row) * STEPS + outbase + col] = tile[p][row][col];
            }
            // no trailing sync: double-buffered; next iteration's barrier
            // orders these reads before the buffer is rewritten
        } else {
            steps16<false>(h, e, c, nstd, nullptr);
        }
    };

    // ping-pong prefetch: next block's 16 noise loads issued before compute
#pragma unroll 1
    for (int blk = 0; blk < nblk; blk += 2) {
        if (blk + 1 < nblk) { load16(eb, np); np += nstride; }
        process(ea, blk);
        if (blk + 1 < nblk) {
            if (blk + 2 < nblk) { load16(ea, np); np += nstride; }
            process(eb, blk + 1);
        }
    }
}

extern "C" void kernel_launch(void* const* d_in, const int* in_sizes, int n_in,
                              void* d_out, int out_size)
{
    const float* iv    = (const float*)d_in[0];
    const float* coef  = (const float*)d_in[1];
    const float* lns   = (const float*)d_in[2];
    const float* noise = (const float*)d_in[3];
    float* out = (float*)d_out;

    dim3 grid(BATCH / BT, NSEG);
    ar_segmented_kernel<<<grid, BT>>>(iv, coef, lns, noise, out);
}

// round 6
// speedup vs baseline: 1.3818x; 1.1204x over previous
#include <cuda_runtime.h>
#include <cuda_bf16.h>
#include <cstdint>
#include <math.h>

// AR(16), batch=4096, steps=8192. Segment-parallel over time: the system is
// stable (|char roots| <= 1/1.1 => decay 0.909/step), so segments 1..31 start
// from a zero state and warm up on the 192 preceding noise steps (residual
// ~1e-8, far under the 1e-3 gate).
//
// R5 = R4 + missing <cstdint>: noise prefetch via cp.async double-buffered
// smem tile (LDGSTS bypasses the RF) -> regs ~56, full-wave residency.
// Output staging folded into the noise tile (read e[k], overwrite with y_k,
// flush transposed with streaming stores).

#define AR_N     16
#define BATCH    4096
#define STEPS    8192
#define TNOISE   (STEPS - AR_N)   /* 8176 */
#define NSEG     32
#define SEGLEN   256              /* last segment: 8176 - 31*256 = 240 */
#define WARM     192              /* (1/1.1)^192 ~ 1e-8 */
#define BT       128              /* batch rows per block */
#define NPAD     132              /* smem row stride (floats): 16B-aligned, low-conflict */

__device__ __forceinline__ void cp16(unsigned dst_smem, const void* src_gmem)
{
    asm volatile("cp.async.cg.shared.global [%0], [%1], 16;\n"
                 :: "r"(dst_smem), "l"(src_gmem));
}

// 16 recurrence steps. e[k] read from smem (bank = (4k+tid)%32 -> conflict-free
// across a warp), y_k overwrites the same slot when EMIT.
template <bool EMIT>
__device__ __forceinline__ void steps16(float h[AR_N], float* __restrict__ sb,
                                        const float c[AR_N], float nstd, int tid)
{
#pragma unroll
    for (int k = 0; k < AR_N; k++) {
        float ek = sb[k * NPAD + tid];
        float a0 = ek * nstd, a1 = 0.f, a2 = 0.f, a3 = 0.f;
#pragma unroll
        for (int i = 0; i < AR_N; i += 4) {
            a0 = fmaf(c[i + 0], h[(k + i + 0) & (AR_N - 1)], a0);
            a1 = fmaf(c[i + 1], h[(k + i + 1) & (AR_N - 1)], a1);
            a2 = fmaf(c[i + 2], h[(k + i + 2) & (AR_N - 1)], a2);
            a3 = fmaf(c[i + 3], h[(k + i + 3) & (AR_N - 1)], a3);
        }
        float nv = (a0 + a1) + (a2 + a3);
        h[k & (AR_N - 1)] = nv;
        if (EMIT) sb[k * NPAD + tid] = nv;
    }
}

__global__ __launch_bounds__(BT) void ar_segmented_kernel(
    const float* __restrict__ iv,     // (BATCH, 16)
    const float* __restrict__ coef,   // (16,)
    const float* __restrict__ lns,    // (1,)
    const float* __restrict__ noise,  // (TNOISE, BATCH)
    float* __restrict__ out)          // (BATCH, STEPS)
{
    __shared__ float nbuf[2][AR_N][NPAD];   // 16.9 KB, double-buffered

    const int tid = threadIdx.x;
    const int s   = blockIdx.y;
    const int rowbase = blockIdx.x * BT;
    const int b   = rowbase + tid;
    const int t0  = s * SEGLEN;
    const int len = (s == NSEG - 1) ? (TNOISE - t0) : SEGLEN;  // 256 or 240
    const float nstd = expf(lns[0]);

    float c[AR_N];
#pragma unroll
    for (int i = 0; i < AR_N; i++) c[i] = __ldg(&coef[i]);

    float h[AR_N];
    int warmblk, tstart;
    if (s == 0) {
        warmblk = 0; tstart = 0;
#pragma unroll
        for (int i = 0; i < AR_N; i++) {
            h[i] = iv[b * AR_N + i];
            out[(size_t)b * STEPS + i] = h[i];
        }
    } else {
        warmblk = WARM / AR_N;  // 12
        tstart  = t0 - WARM;
#pragma unroll
        for (int i = 0; i < AR_N; i++) h[i] = 0.f;
    }
    const int nblk = warmblk + len / AR_N;  // 16 / 28 / 27

    // per-thread cp.async mapping: 4 chunks of 16B; row k = (tid>>5)+4*jj,
    // float column = (tid&31)*4 within this block's 128 batch rows
    const int krow = tid >> 5;
    const int fcol = (tid & 31) * 4;
    const float* gsrc0 = noise + (size_t)rowbase + fcol;
    const unsigned smb = (unsigned)__cvta_generic_to_shared(&nbuf[0][0][0]);

    auto issue_blk = [&](int buf, int trow) {
        const float* g = gsrc0 + (size_t)trow * BATCH;
        unsigned d = smb + (unsigned)(buf * (AR_N * NPAD) + krow * NPAD + fcol) * 4u;
#pragma unroll
        for (int jj = 0; jj < 4; jj++)
            cp16(d + (unsigned)(jj * 4 * NPAD) * 4u,
                 g + (size_t)(krow + jj * 4) * BATCH);
    };

    // prologue: block 0 into buffer 0
    issue_blk(0, tstart);
    asm volatile("cp.async.commit_group;\n");

#pragma unroll 1
    for (int blk = 0; blk < nblk; blk++) {
        const int p = blk & 1;
        if (blk + 1 < nblk) {
            issue_blk(p ^ 1, tstart + (blk + 1) * AR_N);
            asm volatile("cp.async.commit_group;\n");
            asm volatile("cp.async.wait_group 1;\n");
        } else {
            asm volatile("cp.async.wait_group 0;\n");
        }
        __syncthreads();   // buffer p complete & visible; prior flush of p done

        float* sb = &nbuf[p][0][0];
        if (blk >= warmblk) {
            steps16<true>(h, sb, c, nstd, tid);
            __syncthreads();   // y writes complete before transposed reads
            const int outbase = AR_N + t0 + (blk - warmblk) * AR_N;
#pragma unroll
            for (int j = 0; j < AR_N; j++) {
                int fid = j * BT + tid;
                int row = fid >> 4;       // batch row within block
                int col = fid & 15;       // time within blk
                __stcs(&out[(size_t)(rowbase + row) * STEPS + outbase + col],
                       sb[col * NPAD + row]);
            }
        } else {
            steps16<false>(h, sb, c, nstd, tid);
        }
        __syncthreads();   // flush/compute reads done before next cp.async overwrite
    }
}

extern "C" void kernel_launch(void* const* d_in, const int* in_sizes, int n_in,
                              void* d_out, int out_size)
{
    const float* iv    = (const float*)d_in[0];
    const float* coef  = (const float*)d_in[1];
    const float* lns   = (const float*)d_in[2];
    const float* noise = (const float*)d_in[3];
    float* out = (float*)d_out;

    dim3 grid(BATCH / BT, NSEG);
    ar_segmented_kernel<<<grid, BT>>>(iv, coef, lns, noise, out);
}